// round 2
// baseline (speedup 1.0000x reference)
#include <cuda_runtime.h>
#include <cstdint>

// ---------------------------------------------------------------------------
// ValueNetwork forward. Dead-code-eliminated: mlp1/global/attn branch unused.
// Live graph: self6 = state[:,0,:6]; LSTM(64 steps, in=7, hid=50) over
// state[:,:,6:13]; MLP 56->150->100->100->1.
// R2: 32-row LSTM blocks (2 CTAs/SM -> MUFU/GEMM overlap), prep kernel removed
//     (direct strided x reads, latency hidden), LDS.128 weight fetch.
// ---------------------------------------------------------------------------

#define B_SIZE 8192
#define NSTEP  64
#define ROWB   832          // floats per batch row of state (64*13)
#define HID    50
#define KDIM   57           // 7 input + 50 hidden
#define GATE   200
#define WSTR   256          // per-k weight stride (32 lanes * 8 slots, 7 used)
#define RPBL   32           // LSTM rows per block
#define RSTRL  34           // LSTM transposed smem row stride
#define RPBM   64           // MLP rows per block
#define RSTRM  66           // MLP transposed smem row stride
#define THREADS 256

typedef unsigned long long ull;

// scratch (static device array: allocation-free)
__device__ float g_hT[HID * B_SIZE];          // [u][b]: final hidden state

// ---- f32x2 helpers (sm_103a packed fp32 FMA: 2x FFMA throughput) ----------
__device__ __forceinline__ ull dup2(float v) {
    ull r;
    asm("mov.b64 %0, {%1, %1};" : "=l"(r) : "f"(v));
    return r;
}
__device__ __forceinline__ void fma2(ull& d, ull a, ull b) {
    asm("fma.rn.f32x2 %0, %1, %2, %0;" : "+l"(d) : "l"(a), "l"(b));
}
__device__ __forceinline__ float2 unpk(ull v) {
    float2 f;
    asm("mov.b64 {%0, %1}, %2;" : "=f"(f.x), "=f"(f.y) : "l"(v));
    return f;
}

__device__ __forceinline__ float sig_f(float x) {
    return __fdividef(1.f, 1.f + __expf(-x));
}
__device__ __forceinline__ float tanh_f(float x) {
    float xc = fminf(fmaxf(x, -15.f), 15.f);   // avoid exp overflow -> nan
    float e = __expf(2.f * xc);
    return __fdividef(e - 1.f, e + 1.f);
}

// ---------------------------------------------------------------------------
// LSTM: 256 blocks x 32 rows (2 CTAs/SM on 108 SMs: activation MUFU + barriers
// of one block overlap the other's GEMM). Persistent over 64 steps.
// smem: W[57][256] | bias[224] | hx[57][34] | c[50][34] | gates[200][34]
// ---------------------------------------------------------------------------
#define LSTM_SM_FLOATS (KDIM*WSTR + 224 + KDIM*RSTRL + HID*RSTRL + GATE*RSTRL)
#define LSTM_SM_BYTES  (LSTM_SM_FLOATS * 4)

__global__ __launch_bounds__(THREADS, 2) void lstm_kernel(
    const float* __restrict__ state,
    const float* __restrict__ wih, const float* __restrict__ whh,
    const float* __restrict__ bih, const float* __restrict__ bhh)
{
    extern __shared__ float sm[];
    float* Wsh  = sm;                        // 57*256
    float* bsh  = Wsh + KDIM * WSTR;         // 224
    float* hxsh = bsh + 224;                 // 57*34 (rows 0-6 x, 7-56 h)
    float* csh  = hxsh + KDIM * RSTRL;       // 50*34
    float* gsh  = csh + HID * RSTRL;         // 200*34

    const int tid = threadIdx.x;
    const int b0  = blockIdx.x * RPBL;

    // weights: gate col 7*l+j stored at slot (k, 8*l+j); slot j==7 zero pad
    for (int idx = tid; idx < KDIM * WSTR; idx += THREADS) {
        int k = idx >> 8, s = idx & 255, l = s >> 3, j = s & 7;
        int c = l * 7 + j;
        float v = 0.f;
        if (j < 7 && c < GATE)
            v = (k < 7) ? wih[k * GATE + c] : whh[(k - 7) * GATE + c];
        Wsh[idx] = v;
    }
    if (tid < 224) bsh[tid] = (tid < GATE) ? bih[tid] + bhh[tid] : 0.f;
    for (int idx = tid; idx < KDIM * RSTRL; idx += THREADS) hxsh[idx] = 0.f;
    for (int idx = tid; idx < HID * RSTRL; idx += THREADS)  csh[idx]  = 0.f;

    // x(0): 7 contiguous floats per (b, t) row -> near-coalesced gather
    const int xrow = tid / 7, xk = tid - xrow * 7;      // valid for tid<224
    const float* xptr = state + (size_t)(b0 + (tid < 224 ? xrow : 0)) * ROWB
                              + 6 + (tid < 224 ? xk : 0);
    if (tid < 224) hxsh[xk * RSTRL + xrow] = xptr[0];
    __syncthreads();

    const int lane = tid & 31;
    const int warp = tid >> 5;
    const int rb   = warp * 4;               // 8 warps * 4 rows = 32 rows
    const float* wlane = Wsh + (lane << 3);
    const float* hbase = hxsh + rb;

    ull bdup[7];
    #pragma unroll
    for (int j = 0; j < 7; ++j) bdup[j] = dup2(bsh[lane * 7 + j]);

    for (int t = 0; t < NSTEP; ++t) {
        // prefetch x(t+1): LDG latency hidden under the GEMM
        float xv = 0.f;
        {
            int t2 = (t < NSTEP - 1) ? t + 1 : t;
            if (tid < 224) xv = xptr[t2 * 13];
        }

        // gates[32][224] = hx[32][57] @ W[57][224] + bias (f32x2 row-paired)
        ull acc[2][7];
        #pragma unroll
        for (int j = 0; j < 7; ++j) { acc[0][j] = bdup[j]; acc[1][j] = bdup[j]; }

        #pragma unroll 3
        for (int k = 0; k < KDIM; ++k) {
            ull h0 = *(const ull*)(hbase + k * RSTRL);
            ull h1 = *(const ull*)(hbase + k * RSTRL + 2);
            float4 wa = *(const float4*)(wlane + (k << 8));
            float4 wb = *(const float4*)(wlane + (k << 8) + 4);
            float w[7] = {wa.x, wa.y, wa.z, wa.w, wb.x, wb.y, wb.z};
            #pragma unroll
            for (int j = 0; j < 7; ++j) {
                ull w2 = dup2(w[j]);
                fma2(acc[0][j], h0, w2);
                fma2(acc[1][j], h1, w2);
            }
        }
        #pragma unroll
        for (int j = 0; j < 7; ++j) {
            int c = lane * 7 + j;
            if (c < GATE) {
                float* gp = &gsh[c * RSTRL + rb];
                *(ull*)(gp)     = acc[0][j];
                *(ull*)(gp + 2) = acc[1][j];
            }
        }
        __syncthreads();

        // activation / state update (i,f,g,o regroup via gsh)
        for (int idx = tid; idx < HID * RPBL; idx += THREADS) {
            int r = idx & 31, u = idx >> 5;
            float gi = gsh[u * RSTRL + r];
            float gf = gsh[(HID + u) * RSTRL + r];
            float gg = gsh[(2 * HID + u) * RSTRL + r];
            float go = gsh[(3 * HID + u) * RSTRL + r];
            float c  = csh[u * RSTRL + r];
            c = sig_f(gf) * c + sig_f(gi) * tanh_f(gg);
            csh[u * RSTRL + r] = c;
            hxsh[(7 + u) * RSTRL + r] = sig_f(go) * tanh_f(c);
        }
        if (tid < 224) hxsh[xk * RSTRL + xrow] = xv;     // stage x(t+1)
        __syncthreads();
    }

    for (int idx = tid; idx < HID * RPBL; idx += THREADS) {
        int r = idx & 31, u = idx >> 5;
        g_hT[u * B_SIZE + b0 + r] = hxsh[(7 + u) * RSTRL + r];
    }
}

// ---------------------------------------------------------------------------
// MLP: all weights in smem, transposed activation buffers, f32x2 GEMMs.
// ---------------------------------------------------------------------------
template<int IN, int OUT, int LA, int CP>
__device__ __forceinline__ void mlp_layer(const float* __restrict__ Wsh,
                                          const float* __restrict__ Bsh,
                                          const float* __restrict__ Xsh,
                                          float* __restrict__ Ysh,
                                          int lane, int rb)
{
    ull acc[4][CP];
    const bool act = lane < LA;
    #pragma unroll
    for (int j = 0; j < CP; ++j) {
        ull bv = dup2(act ? Bsh[j * LA + lane] : 0.f);
        acc[0][j] = bv; acc[1][j] = bv; acc[2][j] = bv; acc[3][j] = bv;
    }
    #pragma unroll 2
    for (int k = 0; k < IN; ++k) {
        const float* xr = &Xsh[k * RSTRM + rb];
        ull h0 = *(const ull*)(xr);
        ull h1 = *(const ull*)(xr + 2);
        ull h2 = *(const ull*)(xr + 4);
        ull h3 = *(const ull*)(xr + 6);
        #pragma unroll
        for (int j = 0; j < CP; ++j) {
            ull w2 = dup2(act ? Wsh[k * OUT + j * LA + lane] : 0.f);
            fma2(acc[0][j], h0, w2);
            fma2(acc[1][j], h1, w2);
            fma2(acc[2][j], h2, w2);
            fma2(acc[3][j], h3, w2);
        }
    }
    if (act) {
        #pragma unroll
        for (int j = 0; j < CP; ++j) {
            int c = j * LA + lane;
            float* yp = &Ysh[c * RSTRM + rb];
            #pragma unroll
            for (int rp = 0; rp < 4; ++rp) {
                float2 v = unpk(acc[rp][j]);
                v.x = fmaxf(v.x, 0.f);
                v.y = fmaxf(v.y, 0.f);
                *(float2*)(yp + 2 * rp) = v;
            }
        }
    }
}

#define MLP_SM_FLOATS (8400 + 150 + 15000 + 100 + 10000 + 100 + 100 + 2 + 150*RSTRM + 150*RSTRM)
#define MLP_SM_BYTES  (MLP_SM_FLOATS * 4)

__global__ __launch_bounds__(THREADS) void mlp_kernel(
    const float* __restrict__ state,
    const float* __restrict__ w1, const float* __restrict__ b1,
    const float* __restrict__ w2, const float* __restrict__ b2,
    const float* __restrict__ w3, const float* __restrict__ b3,
    const float* __restrict__ w4, const float* __restrict__ b4,
    float* __restrict__ out)
{
    extern __shared__ float sm[];
    float* w1s = sm;                // 8400
    float* b1s = w1s + 8400;        // 150
    float* w2s = b1s + 150;         // 15000
    float* b2s = w2s + 15000;       // 100
    float* w3s = b2s + 100;         // 10000
    float* b3s = w3s + 10000;       // 100
    float* w4s = b3s + 100;         // 100
    float* b4s = w4s + 100;         // 1 (+1 pad)
    float* X   = b4s + 2;           // 150*66
    float* Y   = X + 150 * RSTRM;   // 150*66

    const int tid = threadIdx.x;
    const int b0  = blockIdx.x * RPBM;

    for (int i = tid; i < 8400; i += THREADS)  w1s[i] = w1[i];
    for (int i = tid; i < 15000; i += THREADS) w2s[i] = w2[i];
    for (int i = tid; i < 10000; i += THREADS) w3s[i] = w3[i];
    for (int i = tid; i < 150; i += THREADS)   b1s[i] = b1[i];
    for (int i = tid; i < 100; i += THREADS) {
        b2s[i] = b2[i]; b3s[i] = b3[i]; w4s[i] = w4[i];
    }
    if (tid == 0) b4s[0] = b4[0];
    // joint = [self6 | h]: self6 straight from state[:,0,:6]
    for (int idx = tid; idx < 56 * RPBM; idx += THREADS) {
        int r = idx & 63, k = idx >> 6;
        X[k * RSTRM + r] = (k < 6) ? state[(size_t)(b0 + r) * ROWB + k]
                                   : g_hT[(k - 6) * B_SIZE + b0 + r];
    }
    __syncthreads();

    const int lane = tid & 31;
    const int rb   = (tid >> 5) * 8;

    mlp_layer<56, 150, 30, 5>(w1s, b1s, X, Y, lane, rb);
    __syncthreads();
    mlp_layer<150, 100, 25, 4>(w2s, b2s, Y, X, lane, rb);
    __syncthreads();
    mlp_layer<100, 100, 25, 4>(w3s, b3s, X, Y, lane, rb);
    __syncthreads();

    if (tid < RPBM) {
        float a0 = 0.f, a1 = 0.f, a2 = 0.f, a3 = 0.f;
        #pragma unroll 5
        for (int k = 0; k < 100; k += 4) {
            a0 += Y[k * RSTRM + tid]       * w4s[k];
            a1 += Y[(k + 1) * RSTRM + tid] * w4s[k + 1];
            a2 += Y[(k + 2) * RSTRM + tid] * w4s[k + 2];
            a3 += Y[(k + 3) * RSTRM + tid] * w4s[k + 3];
        }
        out[b0 + tid] = a0 + a1 + a2 + a3 + b4s[0];
    }
}

// ---------------------------------------------------------------------------
extern "C" void kernel_launch(void* const* d_in, const int* in_sizes, int n_in,
                              void* d_out, int out_size)
{
    (void)in_sizes; (void)n_in; (void)out_size;
    const float* state = (const float*)d_in[0];
    const float* wih   = (const float*)d_in[11];
    const float* whh   = (const float*)d_in[12];
    const float* bih   = (const float*)d_in[13];
    const float* bhh   = (const float*)d_in[14];
    const float* w1    = (const float*)d_in[15];
    const float* b1    = (const float*)d_in[16];
    const float* w2    = (const float*)d_in[17];
    const float* b2    = (const float*)d_in[18];
    const float* w3    = (const float*)d_in[19];
    const float* b3    = (const float*)d_in[20];
    const float* w4    = (const float*)d_in[21];
    const float* b4    = (const float*)d_in[22];
    float* out = (float*)d_out;

    cudaFuncSetAttribute(lstm_kernel, cudaFuncAttributeMaxDynamicSharedMemorySize, LSTM_SM_BYTES);
    cudaFuncSetAttribute(mlp_kernel,  cudaFuncAttributeMaxDynamicSharedMemorySize, MLP_SM_BYTES);

    lstm_kernel<<<B_SIZE / RPBL, THREADS, LSTM_SM_BYTES>>>(state, wih, whh, bih, bhh);
    mlp_kernel<<<B_SIZE / RPBM, THREADS, MLP_SM_BYTES>>>(state, w1, b1, w2, b2,
                                                         w3, b3, w4, b4, out);
}

// round 3
// speedup vs baseline: 1.0024x; 1.0024x over previous
#include <cuda_runtime.h>
#include <cstdint>

// ---------------------------------------------------------------------------
// ValueNetwork forward. Dead-code-eliminated: mlp1/global/attn branch unused.
// Live graph: self6 = state[:,0,:6]; LSTM(64 steps, in=7, hid=50) over
// state[:,:,6:13]; MLP 56->150->100->100->1.
// R2: 32-row LSTM blocks (2 CTAs/SM -> MUFU/GEMM overlap), prep kernel removed
//     (direct strided x reads, latency hidden), LDS.128 weight fetch.
// ---------------------------------------------------------------------------

#define B_SIZE 8192
#define NSTEP  64
#define ROWB   832          // floats per batch row of state (64*13)
#define HID    50
#define KDIM   57           // 7 input + 50 hidden
#define GATE   200
#define WSTR   256          // per-k weight stride (32 lanes * 8 slots, 7 used)
#define RPBL   32           // LSTM rows per block
#define RSTRL  34           // LSTM transposed smem row stride
#define RPBM   64           // MLP rows per block
#define RSTRM  66           // MLP transposed smem row stride
#define THREADS 256

typedef unsigned long long ull;

// scratch (static device array: allocation-free)
__device__ float g_hT[HID * B_SIZE];          // [u][b]: final hidden state

// ---- f32x2 helpers (sm_103a packed fp32 FMA: 2x FFMA throughput) ----------
__device__ __forceinline__ ull dup2(float v) {
    ull r;
    asm("mov.b64 %0, {%1, %1};" : "=l"(r) : "f"(v));
    return r;
}
__device__ __forceinline__ void fma2(ull& d, ull a, ull b) {
    asm("fma.rn.f32x2 %0, %1, %2, %0;" : "+l"(d) : "l"(a), "l"(b));
}
__device__ __forceinline__ float2 unpk(ull v) {
    float2 f;
    asm("mov.b64 {%0, %1}, %2;" : "=f"(f.x), "=f"(f.y) : "l"(v));
    return f;
}

__device__ __forceinline__ float sig_f(float x) {
    return __fdividef(1.f, 1.f + __expf(-x));
}
__device__ __forceinline__ float tanh_f(float x) {
    float xc = fminf(fmaxf(x, -15.f), 15.f);   // avoid exp overflow -> nan
    float e = __expf(2.f * xc);
    return __fdividef(e - 1.f, e + 1.f);
}

// ---------------------------------------------------------------------------
// LSTM: 256 blocks x 32 rows (2 CTAs/SM on 108 SMs: activation MUFU + barriers
// of one block overlap the other's GEMM). Persistent over 64 steps.
// smem: W[57][256] | bias[224] | hx[57][34] | c[50][34] | gates[200][34]
// ---------------------------------------------------------------------------
#define LSTM_SM_FLOATS (KDIM*WSTR + 224 + KDIM*RSTRL + HID*RSTRL + GATE*RSTRL)
#define LSTM_SM_BYTES  (LSTM_SM_FLOATS * 4)

__global__ __launch_bounds__(THREADS, 2) void lstm_kernel(
    const float* __restrict__ state,
    const float* __restrict__ wih, const float* __restrict__ whh,
    const float* __restrict__ bih, const float* __restrict__ bhh)
{
    extern __shared__ float sm[];
    float* Wsh  = sm;                        // 57*256
    float* bsh  = Wsh + KDIM * WSTR;         // 224
    float* hxsh = bsh + 224;                 // 57*34 (rows 0-6 x, 7-56 h)
    float* csh  = hxsh + KDIM * RSTRL;       // 50*34
    float* gsh  = csh + HID * RSTRL;         // 200*34

    const int tid = threadIdx.x;
    const int b0  = blockIdx.x * RPBL;

    // weights: gate col 7*l+j stored at slot (k, 8*l+j); slot j==7 zero pad
    for (int idx = tid; idx < KDIM * WSTR; idx += THREADS) {
        int k = idx >> 8, s = idx & 255, l = s >> 3, j = s & 7;
        int c = l * 7 + j;
        float v = 0.f;
        if (j < 7 && c < GATE)
            v = (k < 7) ? wih[k * GATE + c] : whh[(k - 7) * GATE + c];
        Wsh[idx] = v;
    }
    if (tid < 224) bsh[tid] = (tid < GATE) ? bih[tid] + bhh[tid] : 0.f;
    for (int idx = tid; idx < KDIM * RSTRL; idx += THREADS) hxsh[idx] = 0.f;
    for (int idx = tid; idx < HID * RSTRL; idx += THREADS)  csh[idx]  = 0.f;

    // x(0): 7 contiguous floats per (b, t) row -> near-coalesced gather
    const int xrow = tid / 7, xk = tid - xrow * 7;      // valid for tid<224
    const float* xptr = state + (size_t)(b0 + (tid < 224 ? xrow : 0)) * ROWB
                              + 6 + (tid < 224 ? xk : 0);
    if (tid < 224) hxsh[xk * RSTRL + xrow] = xptr[0];
    __syncthreads();

    const int lane = tid & 31;
    const int warp = tid >> 5;
    const int rb   = warp * 4;               // 8 warps * 4 rows = 32 rows
    const float* wlane = Wsh + (lane << 3);
    const float* hbase = hxsh + rb;

    ull bdup[7];
    #pragma unroll
    for (int j = 0; j < 7; ++j) bdup[j] = dup2(bsh[lane * 7 + j]);

    for (int t = 0; t < NSTEP; ++t) {
        // prefetch x(t+1): LDG latency hidden under the GEMM
        float xv = 0.f;
        {
            int t2 = (t < NSTEP - 1) ? t + 1 : t;
            if (tid < 224) xv = xptr[t2 * 13];
        }

        // gates[32][224] = hx[32][57] @ W[57][224] + bias (f32x2 row-paired)
        ull acc[2][7];
        #pragma unroll
        for (int j = 0; j < 7; ++j) { acc[0][j] = bdup[j]; acc[1][j] = bdup[j]; }

        #pragma unroll 3
        for (int k = 0; k < KDIM; ++k) {
            ull h0 = *(const ull*)(hbase + k * RSTRL);
            ull h1 = *(const ull*)(hbase + k * RSTRL + 2);
            float4 wa = *(const float4*)(wlane + (k << 8));
            float4 wb = *(const float4*)(wlane + (k << 8) + 4);
            float w[7] = {wa.x, wa.y, wa.z, wa.w, wb.x, wb.y, wb.z};
            #pragma unroll
            for (int j = 0; j < 7; ++j) {
                ull w2 = dup2(w[j]);
                fma2(acc[0][j], h0, w2);
                fma2(acc[1][j], h1, w2);
            }
        }
        #pragma unroll
        for (int j = 0; j < 7; ++j) {
            int c = lane * 7 + j;
            if (c < GATE) {
                float* gp = &gsh[c * RSTRL + rb];
                *(ull*)(gp)     = acc[0][j];
                *(ull*)(gp + 2) = acc[1][j];
            }
        }
        __syncthreads();

        // activation / state update (i,f,g,o regroup via gsh)
        for (int idx = tid; idx < HID * RPBL; idx += THREADS) {
            int r = idx & 31, u = idx >> 5;
            float gi = gsh[u * RSTRL + r];
            float gf = gsh[(HID + u) * RSTRL + r];
            float gg = gsh[(2 * HID + u) * RSTRL + r];
            float go = gsh[(3 * HID + u) * RSTRL + r];
            float c  = csh[u * RSTRL + r];
            c = sig_f(gf) * c + sig_f(gi) * tanh_f(gg);
            csh[u * RSTRL + r] = c;
            hxsh[(7 + u) * RSTRL + r] = sig_f(go) * tanh_f(c);
        }
        if (tid < 224) hxsh[xk * RSTRL + xrow] = xv;     // stage x(t+1)
        __syncthreads();
    }

    for (int idx = tid; idx < HID * RPBL; idx += THREADS) {
        int r = idx & 31, u = idx >> 5;
        g_hT[u * B_SIZE + b0 + r] = hxsh[(7 + u) * RSTRL + r];
    }
}

// ---------------------------------------------------------------------------
// MLP: all weights in smem, transposed activation buffers, f32x2 GEMMs.
// ---------------------------------------------------------------------------
template<int IN, int OUT, int LA, int CP>
__device__ __forceinline__ void mlp_layer(const float* __restrict__ Wsh,
                                          const float* __restrict__ Bsh,
                                          const float* __restrict__ Xsh,
                                          float* __restrict__ Ysh,
                                          int lane, int rb)
{
    ull acc[4][CP];
    const bool act = lane < LA;
    #pragma unroll
    for (int j = 0; j < CP; ++j) {
        ull bv = dup2(act ? Bsh[j * LA + lane] : 0.f);
        acc[0][j] = bv; acc[1][j] = bv; acc[2][j] = bv; acc[3][j] = bv;
    }
    #pragma unroll 2
    for (int k = 0; k < IN; ++k) {
        const float* xr = &Xsh[k * RSTRM + rb];
        ull h0 = *(const ull*)(xr);
        ull h1 = *(const ull*)(xr + 2);
        ull h2 = *(const ull*)(xr + 4);
        ull h3 = *(const ull*)(xr + 6);
        #pragma unroll
        for (int j = 0; j < CP; ++j) {
            ull w2 = dup2(act ? Wsh[k * OUT + j * LA + lane] : 0.f);
            fma2(acc[0][j], h0, w2);
            fma2(acc[1][j], h1, w2);
            fma2(acc[2][j], h2, w2);
            fma2(acc[3][j], h3, w2);
        }
    }
    if (act) {
        #pragma unroll
        for (int j = 0; j < CP; ++j) {
            int c = j * LA + lane;
            float* yp = &Ysh[c * RSTRM + rb];
            #pragma unroll
            for (int rp = 0; rp < 4; ++rp) {
                float2 v = unpk(acc[rp][j]);
                v.x = fmaxf(v.x, 0.f);
                v.y = fmaxf(v.y, 0.f);
                *(float2*)(yp + 2 * rp) = v;
            }
        }
    }
}

#define MLP_SM_FLOATS (8400 + 150 + 15000 + 100 + 10000 + 100 + 100 + 2 + 150*RSTRM + 150*RSTRM)
#define MLP_SM_BYTES  (MLP_SM_FLOATS * 4)

__global__ __launch_bounds__(THREADS) void mlp_kernel(
    const float* __restrict__ state,
    const float* __restrict__ w1, const float* __restrict__ b1,
    const float* __restrict__ w2, const float* __restrict__ b2,
    const float* __restrict__ w3, const float* __restrict__ b3,
    const float* __restrict__ w4, const float* __restrict__ b4,
    float* __restrict__ out)
{
    extern __shared__ float sm[];
    float* w1s = sm;                // 8400
    float* b1s = w1s + 8400;        // 150
    float* w2s = b1s + 150;         // 15000
    float* b2s = w2s + 15000;       // 100
    float* w3s = b2s + 100;         // 10000
    float* b3s = w3s + 10000;       // 100
    float* w4s = b3s + 100;         // 100
    float* b4s = w4s + 100;         // 1 (+1 pad)
    float* X   = b4s + 2;           // 150*66
    float* Y   = X + 150 * RSTRM;   // 150*66

    const int tid = threadIdx.x;
    const int b0  = blockIdx.x * RPBM;

    for (int i = tid; i < 8400; i += THREADS)  w1s[i] = w1[i];
    for (int i = tid; i < 15000; i += THREADS) w2s[i] = w2[i];
    for (int i = tid; i < 10000; i += THREADS) w3s[i] = w3[i];
    for (int i = tid; i < 150; i += THREADS)   b1s[i] = b1[i];
    for (int i = tid; i < 100; i += THREADS) {
        b2s[i] = b2[i]; b3s[i] = b3[i]; w4s[i] = w4[i];
    }
    if (tid == 0) b4s[0] = b4[0];
    // joint = [self6 | h]: self6 straight from state[:,0,:6]
    for (int idx = tid; idx < 56 * RPBM; idx += THREADS) {
        int r = idx & 63, k = idx >> 6;
        X[k * RSTRM + r] = (k < 6) ? state[(size_t)(b0 + r) * ROWB + k]
                                   : g_hT[(k - 6) * B_SIZE + b0 + r];
    }
    __syncthreads();

    const int lane = tid & 31;
    const int rb   = (tid >> 5) * 8;

    mlp_layer<56, 150, 30, 5>(w1s, b1s, X, Y, lane, rb);
    __syncthreads();
    mlp_layer<150, 100, 25, 4>(w2s, b2s, Y, X, lane, rb);
    __syncthreads();
    mlp_layer<100, 100, 25, 4>(w3s, b3s, X, Y, lane, rb);
    __syncthreads();

    if (tid < RPBM) {
        float a0 = 0.f, a1 = 0.f, a2 = 0.f, a3 = 0.f;
        #pragma unroll 5
        for (int k = 0; k < 100; k += 4) {
            a0 += Y[k * RSTRM + tid]       * w4s[k];
            a1 += Y[(k + 1) * RSTRM + tid] * w4s[k + 1];
            a2 += Y[(k + 2) * RSTRM + tid] * w4s[k + 2];
            a3 += Y[(k + 3) * RSTRM + tid] * w4s[k + 3];
        }
        out[b0 + tid] = a0 + a1 + a2 + a3 + b4s[0];
    }
}

// ---------------------------------------------------------------------------
extern "C" void kernel_launch(void* const* d_in, const int* in_sizes, int n_in,
                              void* d_out, int out_size)
{
    (void)in_sizes; (void)n_in; (void)out_size;
    const float* state = (const float*)d_in[0];
    const float* wih   = (const float*)d_in[11];
    const float* whh   = (const float*)d_in[12];
    const float* bih   = (const float*)d_in[13];
    const float* bhh   = (const float*)d_in[14];
    const float* w1    = (const float*)d_in[15];
    const float* b1    = (const float*)d_in[16];
    const float* w2    = (const float*)d_in[17];
    const float* b2    = (const float*)d_in[18];
    const float* w3    = (const float*)d_in[19];
    const float* b3    = (const float*)d_in[20];
    const float* w4    = (const float*)d_in[21];
    const float* b4    = (const float*)d_in[22];
    float* out = (float*)d_out;

    cudaFuncSetAttribute(lstm_kernel, cudaFuncAttributeMaxDynamicSharedMemorySize, LSTM_SM_BYTES);
    cudaFuncSetAttribute(mlp_kernel,  cudaFuncAttributeMaxDynamicSharedMemorySize, MLP_SM_BYTES);

    lstm_kernel<<<B_SIZE / RPBL, THREADS, LSTM_SM_BYTES>>>(state, wih, whh, bih, bhh);
    mlp_kernel<<<B_SIZE / RPBM, THREADS, MLP_SM_BYTES>>>(state, w1, b1, w2, b2,
                                                         w3, b3, w4, b4, out);
}